// round 4
// baseline (speedup 1.0000x reference)
#include <cuda_runtime.h>

// ThinVesselLoss: EDT only matters through thin = (0 < 2*dist < 3)
// <=> D2 in {1,2} <=> foreground pixel with >=1 in-bounds 8-neighbor
// background pixel. So: 3x3 stencil on (target > 0.5) + weighted BCE + mean.
//
// R3 lesson: problem is parallelism-starved (2048 warps -> occ 20%).
// This version: 4 px/lane -> 8192 warps -> ~86% occupancy. Halo via
// intra-warp shfl; warp-edge columns via 3 clamped scalar loads on
// lanes 0/31 only. Single kernel, fused last-block finalize.

#define B_N 4
#define H_N 512
#define W_N 512
#define NPIX (B_N * H_N * W_N)
#define NTHREADS 256                       // 8 warps/block
#define NBLOCKS  ((B_N * H_N * 4) / 8)     // 8192 warps / 8 = 1024 blocks

__device__ float g_partial[NBLOCKS];
__device__ unsigned g_ticket;              // zero-init; last block resets

__device__ __forceinline__ unsigned m4(float4 v) {
    return (unsigned)(v.x <= 0.5f)
         | ((unsigned)(v.y <= 0.5f) << 1)
         | ((unsigned)(v.z <= 0.5f) << 2)
         | ((unsigned)(v.w <= 0.5f) << 3);
}

__global__ void __launch_bounds__(NTHREADS)
tv_fused(const float* __restrict__ pred, const float* __restrict__ tgt,
         float* __restrict__ out) {
    const int w    = threadIdx.x >> 5;
    const int lane = threadIdx.x & 31;
    const int g    = blockIdx.x * 8 + w;        // global warp 0..8191
    const int row  = g >> 2;                    // 0..2047
    const int seg  = g & 3;                     // 128-col segment
    const int b    = row >> 9;
    const int y    = row & (H_N - 1);
    const long imgbase = (long)b * (H_N * W_N);
    const int  cglob   = seg * 128 + lane * 4;

    const int ym = (y > 0)       ? y - 1 : 0;
    const int yp = (y < H_N - 1) ? y + 1 : H_N - 1;

    // ---- front-batched vector loads: pred + 3 target rows (4 LDG.128) ----
    float4 P  = __ldg(reinterpret_cast<const float4*>(pred + imgbase + (long)y  * W_N + cglob));
    float4 C  = __ldg(reinterpret_cast<const float4*>(tgt  + imgbase + (long)y  * W_N + cglob));
    float4 A  = __ldg(reinterpret_cast<const float4*>(tgt  + imgbase + (long)ym * W_N + cglob));
    float4 Bv = __ldg(reinterpret_cast<const float4*>(tgt  + imgbase + (long)yp * W_N + cglob));

    // ---- 4-bit background mask, 3-row union (vertical edges zeroed) ----
    unsigned M = m4(C)
               | ((y > 0)       ? m4(A)  : 0u)
               | ((y < H_N - 1) ? m4(Bv) : 0u);

    // ---- horizontal halo: intra-warp shfl ----
    unsigned ml = __shfl_up_sync(0xffffffffu, M, 1);
    unsigned mr = __shfl_down_sync(0xffffffffu, M, 1);
    unsigned lbit = (lane == 0)  ? 0u : ((ml >> 3) & 1u);
    unsigned rbit = (lane == 31) ? 0u : (mr & 1u);

    // warp-edge columns: 3 clamped scalar loads on boundary lanes only
    if (lane == 0) {
        const int cl = cglob - 1;
        if (cl >= 0) {
            float ec = __ldg(tgt + imgbase + (long)y  * W_N + cl);
            float ea = __ldg(tgt + imgbase + (long)ym * W_N + cl);
            float eb = __ldg(tgt + imgbase + (long)yp * W_N + cl);
            lbit = (ec <= 0.5f) | ((y > 0) & (ea <= 0.5f)) | ((y < H_N - 1) & (eb <= 0.5f));
        }
    }
    if (lane == 31) {
        const int cr = cglob + 4;
        if (cr < W_N) {
            float ec = __ldg(tgt + imgbase + (long)y  * W_N + cr);
            float ea = __ldg(tgt + imgbase + (long)ym * W_N + cr);
            float eb = __ldg(tgt + imgbase + (long)yp * W_N + cr);
            rbit = (ec <= 0.5f) | ((y > 0) & (ea <= 0.5f)) | ((y < H_N - 1) & (eb <= 0.5f));
        }
    }

    // bit j of M6 = background at col (cglob + j - 1); pixel i window = bits i..i+2
    const unsigned M6 = (M << 1) | lbit | (rbit << 5);

    // ---- weighted BCE for 4 pixels ----
    float pv[4] = {P.x, P.y, P.z, P.w};
    float tv[4] = {C.x, C.y, C.z, C.w};
    float acc = 0.0f;
#pragma unroll
    for (int i = 0; i < 4; i++) {
        const float t  = tv[i];
        const float lp = fmaxf(__logf(pv[i]),        -100.0f);
        const float lq = fmaxf(__logf(1.0f - pv[i]), -100.0f);
        const float bce = -(t * lp + (1.0f - t) * lq);
        const bool thin = (t > 0.5f) && (((M6 >> i) & 7u) != 0u);
        acc += thin ? 3.0f * bce : bce;
    }

    // ---- block reduction ----
#pragma unroll
    for (int off = 16; off > 0; off >>= 1)
        acc += __shfl_xor_sync(0xffffffffu, acc, off);

    __shared__ float ws[8];
    __shared__ bool amLast;
    if (lane == 0) ws[w] = acc;
    __syncthreads();
    if (threadIdx.x == 0) {
        float s = 0.0f;
#pragma unroll
        for (int i = 0; i < 8; i++) s += ws[i];
        g_partial[blockIdx.x] = s;
        __threadfence();
        unsigned t = atomicAdd(&g_ticket, 1u);
        amLast = (t == (unsigned)(gridDim.x - 1));
    }
    __syncthreads();

    // ---- last block: reduce NBLOCKS partials (256 thr x float4 = 1024) ----
    if (amLast) {
        const float4* p4 = reinterpret_cast<const float4*>(g_partial);
        float4 v4 = __ldcg(&p4[threadIdx.x]);
        double v = (double)v4.x + (double)v4.y + (double)v4.z + (double)v4.w;
#pragma unroll
        for (int off = 16; off > 0; off >>= 1)
            v += __shfl_xor_sync(0xffffffffu, v, off);
        __shared__ double ds[8];
        if (lane == 0) ds[w] = v;
        __syncthreads();
        if (threadIdx.x == 0) {
            double s = 0.0;
#pragma unroll
            for (int i = 0; i < 8; i++) s += ds[i];
            out[0] = (float)(s / (double)NPIX);
            g_ticket = 0u;  // reset for next graph replay
        }
    }
}

extern "C" void kernel_launch(void* const* d_in, const int* in_sizes, int n_in,
                              void* d_out, int out_size) {
    const float* pred = (const float*)d_in[0];
    const float* tgt  = (const float*)d_in[1];
    float* out = (float*)d_out;
    (void)in_sizes; (void)n_in; (void)out_size;

    tv_fused<<<NBLOCKS, NTHREADS>>>(pred, tgt, out);
}

// round 5
// speedup vs baseline: 1.2509x; 1.2509x over previous
#include <cuda_runtime.h>

// ThinVesselLoss: EDT only matters through thin = (0 < 2*dist < 3)
// <=> D2 in {1,2} <=> foreground pixel with >=1 in-bounds 8-neighbor
// background pixel. So: 3x3 stencil on (target > 0.5) + weighted BCE + mean.
//
// Reduction: ONE packed 64-bit atomic per block. bits[48:64)=block count,
// bits[0:48)=fixed-point (2^16) sum. Integer adds are associative =>
// bit-exact deterministic. The block that sees count==N-1 in the returned
// old value already holds the global total: no threadfence (no L1 flush!),
// no partials array, no serial re-read tail.

#define B_N 4
#define H_N 512
#define W_N 512
#define NPIX (B_N * H_N * W_N)
#define NTHREADS 256                       // 8 warps/block
#define NBLOCKS  ((B_N * H_N * 4) / 8)     // 8192 warps / 8 = 1024 blocks
#define CNT_ONE  (1ULL << 48)
#define SUM_MASK (CNT_ONE - 1ULL)
#define FIX_SCALE 65536.0

__device__ unsigned long long g_acc;       // zero-init; last block resets

__device__ __forceinline__ unsigned m4(float4 v) {
    return (unsigned)(v.x <= 0.5f)
         | ((unsigned)(v.y <= 0.5f) << 1)
         | ((unsigned)(v.z <= 0.5f) << 2)
         | ((unsigned)(v.w <= 0.5f) << 3);
}

__global__ void __launch_bounds__(NTHREADS)
tv_fused(const float* __restrict__ pred, const float* __restrict__ tgt,
         float* __restrict__ out) {
    const int w    = threadIdx.x >> 5;
    const int lane = threadIdx.x & 31;
    const int g    = blockIdx.x * 8 + w;        // global warp 0..8191
    const int row  = g >> 2;                    // 0..2047
    const int seg  = g & 3;                     // 128-col segment
    const int b    = row >> 9;
    const int y    = row & (H_N - 1);
    const long imgbase = (long)b * (H_N * W_N);
    const int  cglob   = seg * 128 + lane * 4;

    const int ym = (y > 0)       ? y - 1 : 0;
    const int yp = (y < H_N - 1) ? y + 1 : H_N - 1;
    const float* tY  = tgt + imgbase + (long)y  * W_N;
    const float* tYm = tgt + imgbase + (long)ym * W_N;
    const float* tYp = tgt + imgbase + (long)yp * W_N;

    // ---- front-batched loads: 4 x LDG.128 + predicated edge scalars ----
    float4 P  = __ldg(reinterpret_cast<const float4*>(pred + imgbase + (long)y * W_N + cglob));
    float4 C  = __ldg(reinterpret_cast<const float4*>(tY  + cglob));
    float4 A  = __ldg(reinterpret_cast<const float4*>(tYm + cglob));
    float4 Bv = __ldg(reinterpret_cast<const float4*>(tYp + cglob));

    // Edge column: lane 0 needs col cglob-1, lane 31 needs col cglob+4.
    // Clamped address, predicated load, validity folded in afterwards.
    const bool isEdge = (lane == 0) | (lane == 31);
    int ecol = (lane == 0) ? (cglob - 1) : (cglob + 4);
    const bool evalid = isEdge & (ecol >= 0) & (ecol < W_N);
    ecol = min(max(ecol, 0), W_N - 1);
    float ec = 1.0f, ea = 1.0f, eb = 1.0f;     // >0.5 => not background
    if (isEdge) {
        ec = __ldg(tY  + ecol);
        ea = __ldg(tYm + ecol);
        eb = __ldg(tYp + ecol);
    }

    // ---- 4-bit background mask, 3-row union (vertical edges zeroed) ----
    unsigned M = m4(C)
               | ((y > 0)       ? m4(A)  : 0u)
               | ((y < H_N - 1) ? m4(Bv) : 0u);

    unsigned ebit = (unsigned)(evalid &
        ((ec <= 0.5f) | ((y > 0) & (ea <= 0.5f)) | ((y < H_N - 1) & (eb <= 0.5f))));

    // ---- horizontal halo: intra-warp shfl + edge bits ----
    unsigned ml = __shfl_up_sync(0xffffffffu, M, 1);
    unsigned mr = __shfl_down_sync(0xffffffffu, M, 1);
    unsigned lbit = (lane == 0)  ? ebit : ((ml >> 3) & 1u);
    unsigned rbit = (lane == 31) ? ebit : (mr & 1u);

    // bit j of M6 = background at col (cglob + j - 1); pixel i window = bits i..i+2
    const unsigned M6 = (M << 1) | lbit | (rbit << 5);

    // ---- weighted BCE for 4 pixels ----
    float pv[4] = {P.x, P.y, P.z, P.w};
    float tv[4] = {C.x, C.y, C.z, C.w};
    float acc = 0.0f;
#pragma unroll
    for (int i = 0; i < 4; i++) {
        const float t  = tv[i];
        const float lp = fmaxf(__logf(pv[i]),        -100.0f);
        const float lq = fmaxf(__logf(1.0f - pv[i]), -100.0f);
        const float bce = -(t * lp + (1.0f - t) * lq);
        const bool thin = (t > 0.5f) && (((M6 >> i) & 7u) != 0u);
        acc += thin ? 3.0f * bce : bce;
    }

    // ---- block reduction ----
#pragma unroll
    for (int off = 16; off > 0; off >>= 1)
        acc += __shfl_xor_sync(0xffffffffu, acc, off);

    __shared__ float ws[8];
    if (lane == 0) ws[w] = acc;
    __syncthreads();

    // ---- single packed atomic; returned value tells the last block the total ----
    if (threadIdx.x == 0) {
        float s = 0.0f;
#pragma unroll
        for (int i = 0; i < 8; i++) s += ws[i];
        unsigned long long contrib =
            ((unsigned long long)__double2ll_rn((double)s * FIX_SCALE)) | CNT_ONE;
        unsigned long long old = atomicAdd(&g_acc, contrib);
        if ((old >> 48) == (unsigned long long)(NBLOCKS - 1)) {
            unsigned long long total = (old + contrib) & SUM_MASK;
            out[0] = (float)((double)total / FIX_SCALE / (double)NPIX);
            g_acc = 0ULL;   // all contributors finished; reset for next replay
        }
    }
}

extern "C" void kernel_launch(void* const* d_in, const int* in_sizes, int n_in,
                              void* d_out, int out_size) {
    const float* pred = (const float*)d_in[0];
    const float* tgt  = (const float*)d_in[1];
    float* out = (float*)d_out;
    (void)in_sizes; (void)n_in; (void)out_size;

    tv_fused<<<NBLOCKS, NTHREADS>>>(pred, tgt, out);
}